// round 14
// baseline (speedup 1.0000x reference)
#include <cuda_runtime.h>
#include <cuda_bf16.h>
#include <cstdint>

// ---------------- dims ----------------
#define BB 2
#define CIN 64
#define COUT 128
#define CHALF 64
#define HIN 128
#define H 64
#define P (H*H)          // 4096
#define LT 11882
#define LTP 11904        // 93*128
#define K9 576
#define K18 1152
#define NCH 32
#define SCH 372

// ---------------- scratch ----------------
__device__ __align__(128) float g_h0[BB*CIN*P];
__device__ __align__(128) float g_h1[BB*COUT*P];
__device__ __align__(128) float g_h2[BB*COUT*P];
__device__ __align__(128) float g_tmp[BB*COUT*P];
__device__ __align__(128) float g_h3[BB*COUT*P];
__device__ __align__(128) float g_mb[BB*CHALF*P];
__device__ __align__(128) float g_ref[BB*COUT*3249];
__device__ __align__(128) float g_base[(size_t)BB*COUT*LT];
__device__ __align__(128) float g_refm[(size_t)BB*CHALF*LT];
__device__ __align__(128) float g_R[(size_t)BB*LTP*P];        // R = refm^T mb
__device__ __align__(128) float g_scores[(size_t)BB*LTP*P];   // scores / conv partial scratch
__device__ __align__(128) float g_T[(size_t)BB*K18*P];        // attention GEMM partials
__device__ __align__(128) __nv_bfloat16 g_ICh[(size_t)BB*P*K18];
__device__ __align__(128) __nv_bfloat16 g_ICl[(size_t)BB*P*K18];
__device__ __align__(128) __nv_bfloat16 g_Awh[COUT*K18];
__device__ __align__(128) __nv_bfloat16 g_Awl[COUT*K18];
__device__ __align__(128) __nv_bfloat16 g_refmTh[(size_t)BB*LTP*CHALF];
__device__ __align__(128) __nv_bfloat16 g_refmTl[(size_t)BB*LTP*CHALF];
__device__ __align__(128) __nv_bfloat16 g_mbTh[(size_t)BB*P*CHALF];
__device__ __align__(128) __nv_bfloat16 g_mbTl[(size_t)BB*P*CHALF];
__device__ __align__(128) __nv_bfloat16 g_baseTh[(size_t)BB*COUT*LTP];
__device__ __align__(128) __nv_bfloat16 g_baseTl[(size_t)BB*COUT*LTP];
__device__ __align__(128) __nv_bfloat16 g_Gh[(size_t)BB*P*LTP];
__device__ __align__(128) __nv_bfloat16 g_Gl[(size_t)BB*P*LTP];
__device__ __align__(128) float g_E[BB*LTP];
__device__ __align__(128) float g_ninv[BB*LTP];
__device__ __align__(128) float g_pmax[BB*NCH*P];
__device__ __align__(128) float g_psum[BB*NCH*P];

__device__ __forceinline__ void split2(float v, __nv_bfloat16& h, __nv_bfloat16& l) {
    h = __float2bfloat16(v);
    l = __float2bfloat16(v - __bfloat162float(h));
}

__device__ __forceinline__ void decode_l(int l, int& Hs, int& loff) {
    if (l < 4096)      { Hs = 64; loff = 0; }
    else if (l < 7345) { Hs = 57; loff = 4096; }
    else if (l < 9946) { Hs = 51; loff = 7345; }
    else               { Hs = 44; loff = 9946; }
}

// ---------------- maxpool ----------------
__global__ void maxpool_kernel(const float* __restrict__ in, float* __restrict__ out) {
    int idx = blockIdx.x*blockDim.x + threadIdx.x;
    if (idx >= BB*CIN*P) return;
    int x = idx % H; int y = (idx / H) % H; int bc = idx / P;
    const float* p = in + ((size_t)bc*HIN + 2*y)*HIN + 2*x;
    out[idx] = fmaxf(fmaxf(p[0], p[1]), fmaxf(p[HIN], p[HIN+1]));
}

// ---------------- im2col (3x3 pad1), Ci compile-time ----------------
template<int Ci>
__global__ void imcol_kernel(const float* __restrict__ in,
                             __nv_bfloat16* __restrict__ Xh, __nv_bfloat16* __restrict__ Xl) {
    constexpr int K = Ci*9;
    int idx = blockIdx.x*256 + threadIdx.x;
    int b = blockIdx.y;
    if (idx >= P*K) return;
    int k = idx % K; int p = idx / K;
    int c = k/9, r = k%9; int ky = r/3, kx = r - ky*3;
    int y = (p >> 6) + ky - 1, x = (p & 63) + kx - 1;
    float v = 0.f;
    if ((unsigned)y < H && (unsigned)x < H) v = in[((size_t)b*Ci + c)*P + y*H + x];
    __nv_bfloat16 hh, ll; split2(v, hh, ll);
    size_t o = (size_t)b*P*K + idx;
    Xh[o] = hh; Xl[o] = ll;
}

// ---------------- weight split ----------------
__global__ void wsplit_kernel(const float* __restrict__ w,
                              __nv_bfloat16* __restrict__ Ah, __nv_bfloat16* __restrict__ Al,
                              int n) {
    int idx = blockIdx.x*256 + threadIdx.x;
    if (idx >= n) return;
    __nv_bfloat16 hh, ll; split2(w[idx], hh, ll);
    Ah[idx] = hh; Al[idx] = ll;
}

// ---------------- epilogue: scale*sum(partials) + bias + act + residual ----------------
__global__ void epi_kernel(const float* __restrict__ C, const float* __restrict__ bias,
                           const float* __restrict__ alpha_p, const float* __restrict__ res,
                           float* __restrict__ out, int act, float scale,
                           int nsum, size_t sSplit) {
    int idx = blockIdx.x*256 + threadIdx.x;
    if (idx >= BB*COUT*P) return;
    int co = (idx / P) % COUT;
    float v = 0.f;
    for (int i = 0; i < nsum; i++) v += C[idx + (size_t)i*sSplit];
    v = v*scale + (bias ? bias[co] : 0.f);
    if (act == 1) v = fmaxf(v, 0.f);
    else if (act == 2) { float a = *alpha_p; v = v >= 0.f ? v : a*v; }
    if (res) v += res[idx];
    out[idx] = v;
}

// ---------------- 1x1 conv + PReLU, 4 outputs per block ----------------
__global__ void conv1_kernel(const float* __restrict__ in, const float* __restrict__ w,
                             const float* __restrict__ bias, const float* __restrict__ alpha_p,
                             float* __restrict__ out, int Ci, int Co, int Pn) {
    int p = blockIdx.x*256 + threadIdx.x;
    int o0 = blockIdx.y*4, b = blockIdx.z;
    if (p >= Pn) return;
    const float* ip = in + (size_t)b*Ci*Pn + p;
    float acc[4];
    #pragma unroll
    for (int o = 0; o < 4; o++) acc[o] = bias[o0 + o];
    #pragma unroll 4
    for (int i = 0; i < Ci; i++) {
        float t = ip[(size_t)i*Pn];
        #pragma unroll
        for (int o = 0; o < 4; o++) acc[o] += w[(size_t)(o0+o)*Ci + i] * t;
    }
    float a = *alpha_p;
    #pragma unroll
    for (int o = 0; o < 4; o++) {
        float v = acc[o];
        out[((size_t)b*Co + o0 + o)*Pn + p] = v >= 0.f ? v : a*v;
    }
}

// ---------------- bilinear resize with antialias ----------------
__global__ void resize_kernel(const float* __restrict__ in, float* __restrict__ out, int Hout) {
    int total = BB*COUT*Hout*Hout;
    int idx = blockIdx.x*blockDim.x + threadIdx.x;
    if (idx >= total) return;
    int xo = idx % Hout; int yo = (idx / Hout) % Hout; int bc = idx / (Hout*Hout);
    float inv = (float)H / (float)Hout;
    float sy = (yo + 0.5f)*inv - 0.5f;
    float sx = (xo + 0.5f)*inv - 0.5f;
    float wy[4], wx[4]; int jy[4], jx[4];
    int ny = 0, nx = 0; float sumy = 0.f, sumx = 0.f;
    int lo = (int)ceilf(sy - inv), hi = (int)floorf(sy + inv);
    if (lo < 0) lo = 0; if (hi > H-1) hi = H-1;
    for (int j = lo; j <= hi && ny < 4; j++) {
        float w = 1.0f - fabsf(sy - (float)j)/inv;
        if (w > 0.f) { wy[ny] = w; jy[ny] = j; sumy += w; ny++; }
    }
    lo = (int)ceilf(sx - inv); hi = (int)floorf(sx + inv);
    if (lo < 0) lo = 0; if (hi > H-1) hi = H-1;
    for (int j = lo; j <= hi && nx < 4; j++) {
        float w = 1.0f - fabsf(sx - (float)j)/inv;
        if (w > 0.f) { wx[nx] = w; jx[nx] = j; sumx += w; nx++; }
    }
    const float* ip = in + (size_t)bc*P;
    float acc = 0.f;
    for (int a = 0; a < ny; a++)
        for (int bx2 = 0; bx2 < nx; bx2++)
            acc += wy[a]*wx[bx2]*ip[jy[a]*H + jx[bx2]];
    out[idx] = acc / (sumy*sumx);
}

// ---------------- refmT[b][l][c] + E[b][l] ----------------
__global__ void refmT_kernel(const float* __restrict__ refm,
                             __nv_bfloat16* __restrict__ Th, __nv_bfloat16* __restrict__ Tl,
                             float* __restrict__ E) {
    int l = blockIdx.x, b = blockIdx.y, c = threadIdx.x;   // 64 threads
    float v = 0.f;
    if (l < LT) {
        int Hs, loff; decode_l(l, Hs, loff);
        int Ls = Hs*Hs;
        v = refm[(size_t)BB*CHALF*loff + ((size_t)b*CHALF + c)*Ls + (l - loff)];
    }
    __nv_bfloat16 hh, ll; split2(v, hh, ll);
    size_t o = ((size_t)b*LTP + l)*CHALF + c;
    Th[o] = hh; Tl[o] = ll;
    __shared__ float red[64];
    red[c] = v*v; __syncthreads();
    for (int s = 32; s > 0; s >>= 1) { if (c < s) red[c] += red[c+s]; __syncthreads(); }
    if (c == 0) E[(size_t)b*LTP + l] = red[0];
}

// ---------------- ninv[b][l] ----------------
__global__ void ninv_kernel(const float* __restrict__ E, float* __restrict__ ninv) {
    int l = blockIdx.x*256 + threadIdx.x; int b = blockIdx.y;
    if (l >= LT) return;
    int Hs, loff; decode_l(l, Hs, loff);
    int ll = l - loff; int lh = ll/Hs, lw = ll%Hs;
    float a = 0.f;
    #pragma unroll
    for (int u = -1; u <= 1; u++) {
        if ((unsigned)(lh+u) >= (unsigned)Hs) continue;
        #pragma unroll
        for (int v = -1; v <= 1; v++) {
            if ((unsigned)(lw+v) >= (unsigned)Hs) continue;
            a += E[(size_t)b*LTP + l + u*Hs + v];
        }
    }
    ninv[(size_t)b*LTP + l] = 1.0f / fmaxf(sqrtf(a), 1e-4f);
}

// ---------------- mbT split ----------------
__global__ void mbT_kernel(const float* __restrict__ mb,
                           __nv_bfloat16* __restrict__ Th, __nv_bfloat16* __restrict__ Tl) {
    int idx = blockIdx.x*256 + threadIdx.x;
    if (idx >= BB*P*CHALF) return;
    int c = idx % CHALF; int p = (idx / CHALF) % P; int b = idx / (CHALF*P);
    float v = mb[((size_t)b*CHALF + c)*P + p];
    __nv_bfloat16 hh, ll; split2(v, hh, ll);
    Th[idx] = hh; Tl[idx] = ll;
}

// ---------------- baseT split ----------------
__global__ void baseT_kernel(const float* __restrict__ base,
                             __nv_bfloat16* __restrict__ Th, __nv_bfloat16* __restrict__ Tl) {
    int idx = blockIdx.x*256 + threadIdx.x;
    if (idx >= BB*COUT*LTP) return;
    int l = idx % LTP; int c = (idx / LTP) % COUT; int b = idx / (LTP*COUT);
    float v = 0.f;
    if (l < LT) {
        int Hs, loff; decode_l(l, Hs, loff);
        int Ls = Hs*Hs;
        v = base[(size_t)BB*COUT*loff + ((size_t)b*COUT + c)*Ls + (l - loff)];
    }
    __nv_bfloat16 hh, ll; split2(v, hh, ll);
    Th[idx] = hh; Tl[idx] = ll;
}

// ---------------- FUSED assembly + softmax pass 1 ----------------
// per (p, chunk): s(l,p) = ninv[l]*sum9 R, store raw, track max; then exp in place.
__global__ void asm_softmax_kernel(const float* __restrict__ R, const float* __restrict__ ninv,
                                   float* __restrict__ scores,
                                   float* __restrict__ pmax, float* __restrict__ psum) {
    int p = blockIdx.x*256 + threadIdx.x;
    int c = blockIdx.y, b = blockIdx.z;
    int l0 = c*SCH, l1 = l0 + SCH; if (l1 > LT) l1 = LT;
    int py = p >> 6, px = p & 63;
    const float* Rb = R + (size_t)b*LTP*P;
    float* sp = scores + (size_t)b*LTP*P + p;
    const float* nv = ninv + (size_t)b*LTP;

    int Hs, loff; decode_l(l0, Hs, loff);
    int ll = l0 - loff; int lh = ll/Hs, lw = ll - lh*Hs;
    float m = -1e30f;
    for (int l = l0; l < l1; l++) {
        float s = 0.f;
        #pragma unroll
        for (int u = -1; u <= 1; u++) {
            if ((unsigned)(lh+u) >= (unsigned)Hs) continue;
            if ((unsigned)(py+u) >= 64u) continue;
            #pragma unroll
            for (int v = -1; v <= 1; v++) {
                if ((unsigned)(lw+v) >= (unsigned)Hs) continue;
                if ((unsigned)(px+v) >= 64u) continue;
                s += Rb[(size_t)(l + u*Hs + v)*P + p + u*64 + v];
            }
        }
        s *= nv[l];
        sp[(size_t)l*P] = s;
        m = fmaxf(m, s);
        // incremental (lh,lw) update; scale boundaries at exact loffs
        lw++;
        if (lw == Hs) { lw = 0; lh++; }
        int ln = l + 1;
        if (ln == 4096 || ln == 7345 || ln == 9946) {
            decode_l(ln, Hs, loff); lh = 0; lw = 0;
        }
    }
    float sum = 0.f;
    for (int l = l0; l < l1; l++) {
        float e = __expf(10.f*(sp[(size_t)l*P] - m));
        sp[(size_t)l*P] = e;
        sum += e;
    }
    pmax[((size_t)b*NCH + c)*P + p] = m;
    psum[((size_t)b*NCH + c)*P + p] = sum;
}

__global__ void softmax_comb_kernel(const float* __restrict__ pmax, float* __restrict__ psum) {
    int p = blockIdx.x*256 + threadIdx.x; int b = blockIdx.y;
    float M = -1e30f;
    for (int c = 0; c < NCH; c++) M = fmaxf(M, pmax[((size_t)b*NCH + c)*P + p]);
    float S = 0.f;
    for (int c = 0; c < NCH; c++)
        S += psum[((size_t)b*NCH + c)*P + p] * __expf(10.f*(pmax[((size_t)b*NCH + c)*P + p] - M));
    float invS = 1.0f / S;
    for (int c = 0; c < NCH; c++)
        psum[((size_t)b*NCH + c)*P + p] =
            __expf(10.f*(pmax[((size_t)b*NCH + c)*P + p] - M)) * invS;
}

// ---------------- G[b][p][m] = sum9 att, bf16 hi/lo, transposed ----------------
__global__ void G_kernel(const float* __restrict__ scores, const float* __restrict__ psum,
                         __nv_bfloat16* __restrict__ Th, __nv_bfloat16* __restrict__ Tl) {
    __shared__ float t[32][33];
    int p0 = blockIdx.x*32, m0 = blockIdx.y*32, b = blockIdx.z;
    int tx = threadIdx.x, ty = threadIdx.y;
    #pragma unroll
    for (int i = 0; i < 4; i++) {
        int m = m0 + ty + i*8;
        float g = 0.f;
        if (m < LT) {
            int Hs, loff; decode_l(m, Hs, loff);
            int mm = m - loff; int mh = mm/Hs, mw = mm%Hs;
            int p = p0 + tx; int py = p >> 6, px = p & 63;
            #pragma unroll
            for (int u = -1; u <= 1; u++) {
                if ((unsigned)(mh+u) >= (unsigned)Hs) continue;
                if ((unsigned)(py+u) >= 64u) continue;
                #pragma unroll
                for (int v = -1; v <= 1; v++) {
                    if ((unsigned)(mw+v) >= (unsigned)Hs) continue;
                    if ((unsigned)(px+v) >= 64u) continue;
                    int lp = m + u*Hs + v; int pp = p + u*64 + v;
                    g += scores[((size_t)b*LTP + lp)*P + pp] *
                         psum[((size_t)b*NCH + lp/SCH)*P + pp];
                }
            }
        }
        t[ty + i*8][tx] = g;
    }
    __syncthreads();
    #pragma unroll
    for (int i = 0; i < 4; i++) {
        int p = p0 + ty + i*8;
        float v = t[tx][ty + i*8];
        __nv_bfloat16 hh, lo; split2(v, hh, lo);
        size_t o = ((size_t)b*P + p)*LTP + m0 + tx;
        Th[o] = hh; Tl[o] = lo;
    }
}

// ---------------- bf16x3 mma.sync GEMM: CTA 128x128, warp 64x32, 2-stage, occ 2 ----------------
#define AP2 10240
#define STG2 (4*AP2)
#define NSTG2 2

#define LDSM4(R, addr) asm volatile( \
    "ldmatrix.sync.aligned.m8n8.x4.shared.b16 {%0,%1,%2,%3},[%4];" \
    : "=r"((R)[0]),"=r"((R)[1]),"=r"((R)[2]),"=r"((R)[3]) : "r"(addr))
#define MMA16816(d, a, b0, b1) asm volatile( \
    "mma.sync.aligned.m16n8k16.row.col.f32.bf16.bf16.f32 " \
    "{%0,%1,%2,%3},{%4,%5,%6,%7},{%8,%9},{%0,%1,%2,%3};" \
    : "+f"((d)[0]),"+f"((d)[1]),"+f"((d)[2]),"+f"((d)[3]) \
    : "r"((a)[0]),"r"((a)[1]),"r"((a)[2]),"r"((a)[3]),"r"(b0),"r"(b1))
#define CPA16(dst, src) asm volatile( \
    "cp.async.cg.shared.global [%0],[%1],16;" :: "r"(dst),"l"(src))

__global__ __launch_bounds__(256, 2) void gemm3_kernel(
    const __nv_bfloat16* __restrict__ Ah, const __nv_bfloat16* __restrict__ Al,
    const __nv_bfloat16* __restrict__ Bh, const __nv_bfloat16* __restrict__ Bl,
    float* __restrict__ C, int lda, int ldb, int KIT,
    size_t sA, size_t sB, size_t sC,
    int nsplit, int koffE, size_t sSplit)
{
    extern __shared__ char smem[];
    int zz = blockIdx.z;
    int half = zz % nsplit, b = zz / nsplit;
    int kofs = half * koffE;
    const __nv_bfloat16* pAh = Ah + (size_t)b*sA + kofs;
    const __nv_bfloat16* pAl = Al + (size_t)b*sA + kofs;
    const __nv_bfloat16* pBh = Bh + (size_t)b*sB + kofs;
    const __nv_bfloat16* pBl = Bl + (size_t)b*sB + kofs;
    float* pC = C + (size_t)b*sC + (size_t)half*sSplit;
    int row0 = blockIdx.y*128, col0 = blockIdx.x*128;
    int tid = threadIdx.x, lane = tid & 31, wid = tid >> 5;
    int wm = (wid >> 2)*64, wn = (wid & 3)*32;
    uint32_t sb = (uint32_t)__cvta_generic_to_shared(smem);

    float acc[4][4][4];
    #pragma unroll
    for (int i = 0; i < 4; i++)
        #pragma unroll
        for (int j = 0; j < 4; j++)
            #pragma unroll
            for (int r = 0; r < 4; r++) acc[i][j][r] = 0.f;

    auto issue = [&](int it) {
        uint32_t st = sb + (uint32_t)(it & 1)*STG2;
        int k0 = it << 5;
        #pragma unroll
        for (int q = 0; q < 4; q++) {
            int v = tid + q*256;
            int pl = v >> 9, r = (v >> 2) & 127, kv = v & 3;
            const __nv_bfloat16* src = (pl ? pAl : pAh) + (size_t)(row0 + r)*lda + k0 + kv*8;
            CPA16(st + pl*AP2 + (uint32_t)(r*80 + kv*16), src);
        }
        #pragma unroll
        for (int q = 0; q < 4; q++) {
            int v = tid + q*256;
            int pl = v >> 9, n = (v >> 2) & 127, kv = v & 3;
            const __nv_bfloat16* src = (pl ? pBl : pBh) + (size_t)(col0 + n)*ldb + k0 + kv*8;
            CPA16(st + 2*AP2 + pl*AP2 + (uint32_t)(n*80 + kv*16), src);
        }
    };

    issue(0);
    asm volatile("cp.async.commit_group;");

    for (int it = 0; it < KIT; it++) {
        if (it + 1 < KIT) {
            __syncthreads();
            issue(it + 1);
            asm volatile("cp.async.commit_group;");
            asm volatile("cp.async.wait_group 1;");
        } else {
            asm volatile("cp.async.wait_group 0;");
        }
        __syncthreads();
        uint32_t st = sb + (uint32_t)(it & 1)*STG2;
        #pragma unroll
        for (int ks = 0; ks < 2; ks++) {
            int koff = ks*16;
            uint32_t ah[4][4], al_[4][4];
            #pragma unroll
            for (int i = 0; i < 4; i++) {
                uint32_t addr = st + (uint32_t)((wm + i*16 + (lane & 15))*80
                                  + (koff + ((lane >> 4) << 3))*2);
                LDSM4(ah[i], addr);
                LDSM4(al_[i], addr + AP2);
            }
            uint32_t bf0[4], bf1[4];
            {
                uint32_t addr = st + 2*AP2 + (uint32_t)((wn + lane)*80 + koff*2);
                LDSM4(bf0, addr);
                LDSM4(bf1, addr + 16);
            }
            #pragma unroll
            for (int i = 0; i < 4; i++)
                #pragma unroll
                for (int j = 0; j < 4; j++)
                    MMA16816(acc[i][j], ah[i], bf0[j], bf1[j]);
            #pragma unroll
            for (int i = 0; i < 4; i++)
                #pragma unroll
                for (int j = 0; j < 4; j++)
                    MMA16816(acc[i][j], al_[i], bf0[j], bf1[j]);
            {
                uint32_t addr = st + 3*AP2 + (uint32_t)((wn + lane)*80 + koff*2);
                LDSM4(bf0, addr);
                LDSM4(bf1, addr + 16);
            }
            #pragma unroll
            for (int i = 0; i < 4; i++)
                #pragma unroll
                for (int j = 0; j < 4; j++)
                    MMA16816(acc[i][j], ah[i], bf0[j], bf1[j]);
        }
    }

    #pragma unroll
    for (int i = 0; i < 4; i++) {
        int r = row0 + wm + i*16 + (lane >> 2);
        #pragma unroll
        for (int j = 0; j < 4; j++) {
            int c = col0 + wn + j*8 + ((lane & 3) << 1);
            *(float2*)&pC[(size_t)r*4096 + c] = make_float2(acc[i][j][0], acc[i][j][1]);
            *(float2*)&pC[(size_t)(r+8)*4096 + c] = make_float2(acc[i][j][2], acc[i][j][3]);
        }
    }
}

// ---------------- launch ----------------
extern "C" void kernel_launch(void* const* d_in, const int* in_sizes, int n_in,
                              void* d_out, int out_size) {
    (void)in_sizes; (void)n_in; (void)out_size;
    const float* x      = (const float*)d_in[0];
    const float* bb0_w  = (const float*)d_in[1];
    const float* bb0_b  = (const float*)d_in[2];
    const float* bb0_a  = (const float*)d_in[3];
    const float* rb1_w1 = (const float*)d_in[4];
    const float* rb1_b1 = (const float*)d_in[5];
    const float* rb1_w2 = (const float*)d_in[6];
    const float* rb1_b2 = (const float*)d_in[7];
    const float* pamb_w = (const float*)d_in[8];
    const float* pamb_b = (const float*)d_in[9];
    const float* pamb_a = (const float*)d_in[10];
    const float* pam_w  = (const float*)d_in[11];
    const float* pam_b  = (const float*)d_in[12];
    const float* pam_a  = (const float*)d_in[13];
    const float* paa_w  = (const float*)d_in[14];
    const float* paa_b  = (const float*)d_in[15];
    const float* paa_a  = (const float*)d_in[16];
    const float* rb2_w1 = (const float*)d_in[17];
    const float* rb2_b1 = (const float*)d_in[18];
    const float* rb2_w2 = (const float*)d_in[19];
    const float* rb2_b2 = (const float*)d_in[20];
    float* out = (float*)d_out;

    float *h0,*h1,*h2,*tmp,*h3,*mb,*ref,*base,*refm,*R,*scores,*T,*pmax,*psum,*E,*ninv;
    __nv_bfloat16 *ICh,*ICl,*Awh,*Awl,*refmTh,*refmTl,*mbTh,*mbTl,*baseTh,*baseTl,*Gh,*Gl;
    cudaGetSymbolAddress((void**)&h0, g_h0);
    cudaGetSymbolAddress((void**)&h1, g_h1);
    cudaGetSymbolAddress((void**)&h2, g_h2);
    cudaGetSymbolAddress((void**)&tmp, g_tmp);
    cudaGetSymbolAddress((void**)&h3, g_h3);
    cudaGetSymbolAddress((void**)&mb, g_mb);
    cudaGetSymbolAddress((void**)&ref, g_ref);
    cudaGetSymbolAddress((void**)&base, g_base);
    cudaGetSymbolAddress((void**)&refm, g_refm);
    cudaGetSymbolAddress((void**)&R, g_R);
    cudaGetSymbolAddress((void**)&scores, g_scores);
    cudaGetSymbolAddress((void**)&T, g_T);
    cudaGetSymbolAddress((void**)&ICh, g_ICh);
    cudaGetSymbolAddress((void**)&ICl, g_ICl);
    cudaGetSymbolAddress((void**)&Awh, g_Awh);
    cudaGetSymbolAddress((void**)&Awl, g_Awl);
    cudaGetSymbolAddress((void**)&refmTh, g_refmTh);
    cudaGetSymbolAddress((void**)&refmTl, g_refmTl);
    cudaGetSymbolAddress((void**)&mbTh, g_mbTh);
    cudaGetSymbolAddress((void**)&mbTl, g_mbTl);
    cudaGetSymbolAddress((void**)&baseTh, g_baseTh);
    cudaGetSymbolAddress((void**)&baseTl, g_baseTl);
    cudaGetSymbolAddress((void**)&Gh, g_Gh);
    cudaGetSymbolAddress((void**)&Gl, g_Gl);
    cudaGetSymbolAddress((void**)&E, g_E);
    cudaGetSymbolAddress((void**)&ninv, g_ninv);
    cudaGetSymbolAddress((void**)&pmax, g_pmax);
    cudaGetSymbolAddress((void**)&psum, g_psum);

    cudaFuncSetAttribute(gemm3_kernel, cudaFuncAttributeMaxDynamicSharedMemorySize, NSTG2*STG2);

    float* Craw = scores;
    auto conv3g = [&](const float* in, const float* w, const float* bias,
                      const float* alpha, const float* res, float* o, int Ci, int act) {
        int K = Ci*9;
        int split = (Ci == CIN) ? 2 : 4;     // Kh/32 integral: 288/32=9 both ways
        int Kh = K/split;
        wsplit_kernel<<<(COUT*K + 255)/256, 256>>>(w, Awh, Awl, COUT*K);
        if (Ci == CIN)
            imcol_kernel<CIN><<<dim3((P*CIN*9 + 255)/256, BB), 256>>>(in, ICh, ICl);
        else
            imcol_kernel<COUT><<<dim3((P*COUT*9 + 255)/256, BB), 256>>>(in, ICh, ICl);
        gemm3_kernel<<<dim3(P/128, 1, BB*split), 256, NSTG2*STG2>>>(
            Awh, Awl, ICh, ICl, Craw, K, K, Kh/32,
            0, (size_t)P*K, (size_t)COUT*P,
            split, Kh, (size_t)BB*COUT*P);
        epi_kernel<<<(BB*COUT*P + 255)/256, 256>>>(Craw, bias, alpha, res, o, act,
                                                   1.0f, split, (size_t)BB*COUT*P);
    };

    maxpool_kernel<<<(BB*CIN*P + 255)/256, 256>>>(x, h0);
    conv3g(h0, bb0_w, bb0_b, bb0_a, nullptr, h1, CIN, 2);
    conv3g(h1, rb1_w1, rb1_b1, nullptr, nullptr, tmp, COUT, 1);
    conv3g(tmp, rb1_w2, rb1_b2, nullptr, h1, h2, COUT, 0);

    // pyramid producers
    conv1_kernel<<<dim3(P/256, CHALF/4, BB), 256>>>(h2, pamb_w, pamb_b, pamb_a, mb, COUT, CHALF, P);
    const int Hs[4]   = {64, 57, 51, 44};
    const int loff[4] = {0, 4096, 7345, 9946};
    for (int s = 0; s < 4; s++) {
        int Ls = Hs[s]*Hs[s];
        const float* refp;
        if (s == 0) refp = h2;
        else {
            int n = BB*COUT*Ls;
            resize_kernel<<<(n + 255)/256, 256>>>(h2, ref, Hs[s]);
            refp = ref;
        }
        conv1_kernel<<<dim3((Ls + 255)/256, COUT/4, BB), 256>>>(
            refp, paa_w, paa_b, paa_a, base + (size_t)BB*COUT*loff[s], COUT, COUT, Ls);
        conv1_kernel<<<dim3((Ls + 255)/256, CHALF/4, BB), 256>>>(
            refp, pam_w, pam_b, pam_a, refm + (size_t)BB*CHALF*loff[s], COUT, CHALF, Ls);
    }

    mbT_kernel<<<(BB*P*CHALF + 255)/256, 256>>>(mb, mbTh, mbTl);
    refmT_kernel<<<dim3(LTP, BB), 64>>>(refm, refmTh, refmTl, E);
    ninv_kernel<<<dim3((LT + 255)/256, BB), 256>>>(E, ninv);
    baseT_kernel<<<(BB*COUT*LTP + 255)/256, 256>>>(base, baseTh, baseTl);

    // R[m][p] = refm^T mb  (M=LTP, N=4096, K=64)
    gemm3_kernel<<<dim3(P/128, LTP/128, BB), 256, NSTG2*STG2>>>(
        refmTh, refmTl, mbTh, mbTl, R, CHALF, CHALF, CHALF/32,
        (size_t)LTP*CHALF, (size_t)P*CHALF, (size_t)LTP*P,
        1, 0, 0);

    // fused: scores from R (9-pt, normalized) + softmax pass 1
    asm_softmax_kernel<<<dim3(P/256, NCH, BB), 256>>>(R, ninv, scores, pmax, psum);
    softmax_comb_kernel<<<dim3(P/256, BB), 256>>>(pmax, psum);

    // G = 9-point diagonal sum of attention, transposed + bf16 split
    G_kernel<<<dim3(P/32, LTP/32, BB), dim3(32,8)>>>(scores, psum, Gh, Gl);

    // out_raw = base x G  (M=128, N=4096, K=LTP), split-K x6 -> grid 384
    gemm3_kernel<<<dim3(P/128, 1, BB*6), 256, NSTG2*STG2>>>(
        baseTh, baseTl, Gh, Gl, T, LTP, LTP, (LTP/6)/32,
        (size_t)COUT*LTP, (size_t)P*LTP, (size_t)COUT*P,
        6, LTP/6, (size_t)BB*COUT*P);

    // h3 = h2 + 0.25*sum(partials)
    epi_kernel<<<(BB*COUT*P + 255)/256, 256>>>(T, nullptr, nullptr, h2, h3, 0,
                                               0.25f, 6, (size_t)BB*COUT*P);

    conv3g(h3, rb2_w1, rb2_b1, nullptr, nullptr, tmp, COUT, 1);
    conv3g(tmp, rb2_w2, rb2_b2, nullptr, h3, out, COUT, 0);
}

// round 15
// speedup vs baseline: 1.0271x; 1.0271x over previous
#include <cuda_runtime.h>
#include <cuda_bf16.h>
#include <cstdint>

// ---------------- dims ----------------
#define BB 2
#define CIN 64
#define COUT 128
#define CHALF 64
#define HIN 128
#define H 64
#define P (H*H)          // 4096
#define LT 11882
#define LTP 11904        // 93*128
#define K9 576
#define K18 1152
#define NCH 32
#define SCH 372

// ---------------- scratch ----------------
__device__ __align__(128) float g_h0[BB*CIN*P];
__device__ __align__(128) float g_h1[BB*COUT*P];
__device__ __align__(128) float g_h2[BB*COUT*P];
__device__ __align__(128) float g_tmp[BB*COUT*P];
__device__ __align__(128) float g_h3[BB*COUT*P];
__device__ __align__(128) float g_mb[BB*CHALF*P];
__device__ __align__(128) float g_ref[BB*COUT*3249];
__device__ __align__(128) float g_base[(size_t)BB*COUT*LT];
__device__ __align__(128) float g_refm[(size_t)BB*CHALF*LT];
__device__ __align__(128) float g_R[(size_t)BB*LTP*P];        // R = refm^T mb
__device__ __align__(128) float g_scores[(size_t)BB*LTP*P];   // scores / conv partial scratch
__device__ __align__(128) float g_T[(size_t)BB*K18*P];        // attention GEMM partials
__device__ __align__(128) __nv_bfloat16 g_ICh[(size_t)BB*P*K18];
__device__ __align__(128) __nv_bfloat16 g_ICl[(size_t)BB*P*K18];
__device__ __align__(128) __nv_bfloat16 g_Awh[COUT*K18];
__device__ __align__(128) __nv_bfloat16 g_Awl[COUT*K18];
__device__ __align__(128) __nv_bfloat16 g_refmTh[(size_t)BB*LTP*CHALF];
__device__ __align__(128) __nv_bfloat16 g_refmTl[(size_t)BB*LTP*CHALF];
__device__ __align__(128) __nv_bfloat16 g_mbTh[(size_t)BB*P*CHALF];
__device__ __align__(128) __nv_bfloat16 g_mbTl[(size_t)BB*P*CHALF];
__device__ __align__(128) __nv_bfloat16 g_baseTh[(size_t)BB*COUT*LTP];
__device__ __align__(128) __nv_bfloat16 g_baseTl[(size_t)BB*COUT*LTP];
__device__ __align__(128) __nv_bfloat16 g_Gh[(size_t)BB*P*LTP];
__device__ __align__(128) __nv_bfloat16 g_Gl[(size_t)BB*P*LTP];
__device__ __align__(128) float g_E[BB*LTP];
__device__ __align__(128) float g_ninv[BB*LTP];
__device__ __align__(128) float g_pmax[BB*NCH*P];
__device__ __align__(128) float g_psum[BB*NCH*P];

__device__ __forceinline__ void split2(float v, __nv_bfloat16& h, __nv_bfloat16& l) {
    h = __float2bfloat16(v);
    l = __float2bfloat16(v - __bfloat162float(h));
}

__device__ __forceinline__ void decode_l(int l, int& Hs, int& loff) {
    if (l < 4096)      { Hs = 64; loff = 0; }
    else if (l < 7345) { Hs = 57; loff = 4096; }
    else if (l < 9946) { Hs = 51; loff = 7345; }
    else               { Hs = 44; loff = 9946; }
}

// ---------------- maxpool ----------------
__global__ void maxpool_kernel(const float* __restrict__ in, float* __restrict__ out) {
    int idx = blockIdx.x*blockDim.x + threadIdx.x;
    if (idx >= BB*CIN*P) return;
    int x = idx % H; int y = (idx / H) % H; int bc = idx / P;
    const float* p = in + ((size_t)bc*HIN + 2*y)*HIN + 2*x;
    out[idx] = fmaxf(fmaxf(p[0], p[1]), fmaxf(p[HIN], p[HIN+1]));
}

// ---------------- im2col (3x3 pad1), Ci compile-time ----------------
template<int Ci>
__global__ void imcol_kernel(const float* __restrict__ in,
                             __nv_bfloat16* __restrict__ Xh, __nv_bfloat16* __restrict__ Xl) {
    constexpr int K = Ci*9;
    int idx = blockIdx.x*256 + threadIdx.x;
    int b = blockIdx.y;
    if (idx >= P*K) return;
    int k = idx % K; int p = idx / K;
    int c = k/9, r = k%9; int ky = r/3, kx = r - ky*3;
    int y = (p >> 6) + ky - 1, x = (p & 63) + kx - 1;
    float v = 0.f;
    if ((unsigned)y < H && (unsigned)x < H) v = in[((size_t)b*Ci + c)*P + y*H + x];
    __nv_bfloat16 hh, ll; split2(v, hh, ll);
    size_t o = (size_t)b*P*K + idx;
    Xh[o] = hh; Xl[o] = ll;
}

// ---------------- weight split ----------------
__global__ void wsplit_kernel(const float* __restrict__ w,
                              __nv_bfloat16* __restrict__ Ah, __nv_bfloat16* __restrict__ Al,
                              int n) {
    int idx = blockIdx.x*256 + threadIdx.x;
    if (idx >= n) return;
    __nv_bfloat16 hh, ll; split2(w[idx], hh, ll);
    Ah[idx] = hh; Al[idx] = ll;
}

// ---------------- epilogue: scale*sum(partials) + bias + act + residual ----------------
__global__ void epi_kernel(const float* __restrict__ C, const float* __restrict__ bias,
                           const float* __restrict__ alpha_p, const float* __restrict__ res,
                           float* __restrict__ out, int act, float scale,
                           int nsum, size_t sSplit) {
    int idx = blockIdx.x*256 + threadIdx.x;
    if (idx >= BB*COUT*P) return;
    int co = (idx / P) % COUT;
    float v = 0.f;
    for (int i = 0; i < nsum; i++) v += C[idx + (size_t)i*sSplit];
    v = v*scale + (bias ? bias[co] : 0.f);
    if (act == 1) v = fmaxf(v, 0.f);
    else if (act == 2) { float a = *alpha_p; v = v >= 0.f ? v : a*v; }
    if (res) v += res[idx];
    out[idx] = v;
}

// ---------------- 1x1 conv + PReLU, 4 outputs per block ----------------
__global__ void conv1_kernel(const float* __restrict__ in, const float* __restrict__ w,
                             const float* __restrict__ bias, const float* __restrict__ alpha_p,
                             float* __restrict__ out, int Ci, int Co, int Pn) {
    int p = blockIdx.x*256 + threadIdx.x;
    int o0 = blockIdx.y*4, b = blockIdx.z;
    if (p >= Pn) return;
    const float* ip = in + (size_t)b*Ci*Pn + p;
    float acc[4];
    #pragma unroll
    for (int o = 0; o < 4; o++) acc[o] = bias[o0 + o];
    #pragma unroll 4
    for (int i = 0; i < Ci; i++) {
        float t = ip[(size_t)i*Pn];
        #pragma unroll
        for (int o = 0; o < 4; o++) acc[o] += w[(size_t)(o0+o)*Ci + i] * t;
    }
    float a = *alpha_p;
    #pragma unroll
    for (int o = 0; o < 4; o++) {
        float v = acc[o];
        out[((size_t)b*Co + o0 + o)*Pn + p] = v >= 0.f ? v : a*v;
    }
}

// ---------------- bilinear resize with antialias ----------------
__global__ void resize_kernel(const float* __restrict__ in, float* __restrict__ out, int Hout) {
    int total = BB*COUT*Hout*Hout;
    int idx = blockIdx.x*blockDim.x + threadIdx.x;
    if (idx >= total) return;
    int xo = idx % Hout; int yo = (idx / Hout) % Hout; int bc = idx / (Hout*Hout);
    float inv = (float)H / (float)Hout;
    float sy = (yo + 0.5f)*inv - 0.5f;
    float sx = (xo + 0.5f)*inv - 0.5f;
    float wy[4], wx[4]; int jy[4], jx[4];
    int ny = 0, nx = 0; float sumy = 0.f, sumx = 0.f;
    int lo = (int)ceilf(sy - inv), hi = (int)floorf(sy + inv);
    if (lo < 0) lo = 0; if (hi > H-1) hi = H-1;
    for (int j = lo; j <= hi && ny < 4; j++) {
        float w = 1.0f - fabsf(sy - (float)j)/inv;
        if (w > 0.f) { wy[ny] = w; jy[ny] = j; sumy += w; ny++; }
    }
    lo = (int)ceilf(sx - inv); hi = (int)floorf(sx + inv);
    if (lo < 0) lo = 0; if (hi > H-1) hi = H-1;
    for (int j = lo; j <= hi && nx < 4; j++) {
        float w = 1.0f - fabsf(sx - (float)j)/inv;
        if (w > 0.f) { wx[nx] = w; jx[nx] = j; sumx += w; nx++; }
    }
    const float* ip = in + (size_t)bc*P;
    float acc = 0.f;
    for (int a = 0; a < ny; a++)
        for (int bx2 = 0; bx2 < nx; bx2++)
            acc += wy[a]*wx[bx2]*ip[jy[a]*H + jx[bx2]];
    out[idx] = acc / (sumy*sumx);
}

// ---------------- refmT[b][l][c] + E[b][l] ----------------
__global__ void refmT_kernel(const float* __restrict__ refm,
                             __nv_bfloat16* __restrict__ Th, __nv_bfloat16* __restrict__ Tl,
                             float* __restrict__ E) {
    int l = blockIdx.x, b = blockIdx.y, c = threadIdx.x;   // 64 threads
    float v = 0.f;
    if (l < LT) {
        int Hs, loff; decode_l(l, Hs, loff);
        int Ls = Hs*Hs;
        v = refm[(size_t)BB*CHALF*loff + ((size_t)b*CHALF + c)*Ls + (l - loff)];
    }
    __nv_bfloat16 hh, ll; split2(v, hh, ll);
    size_t o = ((size_t)b*LTP + l)*CHALF + c;
    Th[o] = hh; Tl[o] = ll;
    __shared__ float red[64];
    red[c] = v*v; __syncthreads();
    for (int s = 32; s > 0; s >>= 1) { if (c < s) red[c] += red[c+s]; __syncthreads(); }
    if (c == 0) E[(size_t)b*LTP + l] = red[0];
}

// ---------------- ninv[b][l] ----------------
__global__ void ninv_kernel(const float* __restrict__ E, float* __restrict__ ninv) {
    int l = blockIdx.x*256 + threadIdx.x; int b = blockIdx.y;
    if (l >= LT) return;
    int Hs, loff; decode_l(l, Hs, loff);
    int ll = l - loff; int lh = ll/Hs, lw = ll%Hs;
    float a = 0.f;
    #pragma unroll
    for (int u = -1; u <= 1; u++) {
        if ((unsigned)(lh+u) >= (unsigned)Hs) continue;
        #pragma unroll
        for (int v = -1; v <= 1; v++) {
            if ((unsigned)(lw+v) >= (unsigned)Hs) continue;
            a += E[(size_t)b*LTP + l + u*Hs + v];
        }
    }
    ninv[(size_t)b*LTP + l] = 1.0f / fmaxf(sqrtf(a), 1e-4f);
}

// ---------------- mbT split ----------------
__global__ void mbT_kernel(const float* __restrict__ mb,
                           __nv_bfloat16* __restrict__ Th, __nv_bfloat16* __restrict__ Tl) {
    int idx = blockIdx.x*256 + threadIdx.x;
    if (idx >= BB*P*CHALF) return;
    int c = idx % CHALF; int p = (idx / CHALF) % P; int b = idx / (CHALF*P);
    float v = mb[((size_t)b*CHALF + c)*P + p];
    __nv_bfloat16 hh, ll; split2(v, hh, ll);
    Th[idx] = hh; Tl[idx] = ll;
}

// ---------------- baseT split ----------------
__global__ void baseT_kernel(const float* __restrict__ base,
                             __nv_bfloat16* __restrict__ Th, __nv_bfloat16* __restrict__ Tl) {
    int idx = blockIdx.x*256 + threadIdx.x;
    if (idx >= BB*COUT*LTP) return;
    int l = idx % LTP; int c = (idx / LTP) % COUT; int b = idx / (LTP*COUT);
    float v = 0.f;
    if (l < LT) {
        int Hs, loff; decode_l(l, Hs, loff);
        int Ls = Hs*Hs;
        v = base[(size_t)BB*COUT*loff + ((size_t)b*COUT + c)*Ls + (l - loff)];
    }
    __nv_bfloat16 hh, ll; split2(v, hh, ll);
    Th[idx] = hh; Tl[idx] = ll;
}

// ---------------- assembly: scores[l][p] = ninv[l] * sum_{u,v} R[l+(u,v)][p+(u,v)] ----------------
__global__ void assembly_kernel(const float* __restrict__ R, const float* __restrict__ ninv,
                                float* __restrict__ scores) {
    int p = blockIdx.x*256 + threadIdx.x;
    int l = blockIdx.y, b = blockIdx.z;
    int Hs, loff; decode_l(l, Hs, loff);
    int ll = l - loff; int lh = ll/Hs, lw = ll%Hs;
    int py = p >> 6, px = p & 63;
    float s = 0.f;
    #pragma unroll
    for (int u = -1; u <= 1; u++) {
        if ((unsigned)(lh+u) >= (unsigned)Hs) continue;
        if ((unsigned)(py+u) >= 64u) continue;
        #pragma unroll
        for (int v = -1; v <= 1; v++) {
            if ((unsigned)(lw+v) >= (unsigned)Hs) continue;
            if ((unsigned)(px+v) >= 64u) continue;
            s += R[((size_t)b*LTP + l + u*Hs + v)*P + p + u*64 + v];
        }
    }
    scores[((size_t)b*LTP + l)*P + p] = s * ninv[(size_t)b*LTP + l];
}

// ---------------- softmax pass 1 (stores exp in place) ----------------
__global__ void softmax_part_kernel(float* __restrict__ scores,
                                    float* __restrict__ pmax, float* __restrict__ psum) {
    int p = blockIdx.x*256 + threadIdx.x;
    int c = blockIdx.y, b = blockIdx.z;
    int l0 = c*SCH, l1 = l0 + SCH; if (l1 > LT) l1 = LT;
    float* s = scores + (size_t)b*LTP*P + p;
    float m = -1e30f;
    for (int l = l0; l < l1; l++) m = fmaxf(m, s[(size_t)l*P]);
    float sum = 0.f;
    for (int l = l0; l < l1; l++) {
        float e = __expf(10.f*(s[(size_t)l*P] - m));
        s[(size_t)l*P] = e;
        sum += e;
    }
    pmax[((size_t)b*NCH + c)*P + p] = m;
    psum[((size_t)b*NCH + c)*P + p] = sum;
}

__global__ void softmax_comb_kernel(const float* __restrict__ pmax, float* __restrict__ psum) {
    int p = blockIdx.x*256 + threadIdx.x; int b = blockIdx.y;
    float M = -1e30f;
    for (int c = 0; c < NCH; c++) M = fmaxf(M, pmax[((size_t)b*NCH + c)*P + p]);
    float S = 0.f;
    for (int c = 0; c < NCH; c++)
        S += psum[((size_t)b*NCH + c)*P + p] * __expf(10.f*(pmax[((size_t)b*NCH + c)*P + p] - M));
    float invS = 1.0f / S;
    for (int c = 0; c < NCH; c++)
        psum[((size_t)b*NCH + c)*P + p] =
            __expf(10.f*(pmax[((size_t)b*NCH + c)*P + p] - M)) * invS;
}

// ---------------- G[b][p][m] = sum9 att, bf16 hi/lo, transposed ----------------
__global__ void G_kernel(const float* __restrict__ scores, const float* __restrict__ psum,
                         __nv_bfloat16* __restrict__ Th, __nv_bfloat16* __restrict__ Tl) {
    __shared__ float t[32][33];
    int p0 = blockIdx.x*32, m0 = blockIdx.y*32, b = blockIdx.z;
    int tx = threadIdx.x, ty = threadIdx.y;
    #pragma unroll
    for (int i = 0; i < 4; i++) {
        int m = m0 + ty + i*8;
        float g = 0.f;
        if (m < LT) {
            int Hs, loff; decode_l(m, Hs, loff);
            int mm = m - loff; int mh = mm/Hs, mw = mm%Hs;
            int p = p0 + tx; int py = p >> 6, px = p & 63;
            #pragma unroll
            for (int u = -1; u <= 1; u++) {
                if ((unsigned)(mh+u) >= (unsigned)Hs) continue;
                if ((unsigned)(py+u) >= 64u) continue;
                #pragma unroll
                for (int v = -1; v <= 1; v++) {
                    if ((unsigned)(mw+v) >= (unsigned)Hs) continue;
                    if ((unsigned)(px+v) >= 64u) continue;
                    int lp = m + u*Hs + v; int pp = p + u*64 + v;
                    g += scores[((size_t)b*LTP + lp)*P + pp] *
                         psum[((size_t)b*NCH + lp/SCH)*P + pp];
                }
            }
        }
        t[ty + i*8][tx] = g;
    }
    __syncthreads();
    #pragma unroll
    for (int i = 0; i < 4; i++) {
        int p = p0 + ty + i*8;
        float v = t[tx][ty + i*8];
        __nv_bfloat16 hh, lo; split2(v, hh, lo);
        size_t o = ((size_t)b*P + p)*LTP + m0 + tx;
        Th[o] = hh; Tl[o] = lo;
    }
}

// ---------------- bf16x3 mma.sync GEMM: CTA 128x128, warp 64x32, 2-stage, occ 2 ----------------
#define AP2 10240
#define STG2 (4*AP2)
#define NSTG2 2

#define LDSM4(R, addr) asm volatile( \
    "ldmatrix.sync.aligned.m8n8.x4.shared.b16 {%0,%1,%2,%3},[%4];" \
    : "=r"((R)[0]),"=r"((R)[1]),"=r"((R)[2]),"=r"((R)[3]) : "r"(addr))
#define MMA16816(d, a, b0, b1) asm volatile( \
    "mma.sync.aligned.m16n8k16.row.col.f32.bf16.bf16.f32 " \
    "{%0,%1,%2,%3},{%4,%5,%6,%7},{%8,%9},{%0,%1,%2,%3};" \
    : "+f"((d)[0]),"+f"((d)[1]),"+f"((d)[2]),"+f"((d)[3]) \
    : "r"((a)[0]),"r"((a)[1]),"r"((a)[2]),"r"((a)[3]),"r"(b0),"r"(b1))
#define CPA16(dst, src) asm volatile( \
    "cp.async.cg.shared.global [%0],[%1],16;" :: "r"(dst),"l"(src))

__global__ __launch_bounds__(256, 2) void gemm3_kernel(
    const __nv_bfloat16* __restrict__ Ah, const __nv_bfloat16* __restrict__ Al,
    const __nv_bfloat16* __restrict__ Bh, const __nv_bfloat16* __restrict__ Bl,
    float* __restrict__ C, int lda, int ldb, int KIT,
    size_t sA, size_t sB, size_t sC,
    int nsplit, int koffE, size_t sSplit)
{
    extern __shared__ char smem[];
    int zz = blockIdx.z;
    int half = zz % nsplit, b = zz / nsplit;
    int kofs = half * koffE;
    const __nv_bfloat16* pAh = Ah + (size_t)b*sA + kofs;
    const __nv_bfloat16* pAl = Al + (size_t)b*sA + kofs;
    const __nv_bfloat16* pBh = Bh + (size_t)b*sB + kofs;
    const __nv_bfloat16* pBl = Bl + (size_t)b*sB + kofs;
    float* pC = C + (size_t)b*sC + (size_t)half*sSplit;
    int row0 = blockIdx.y*128, col0 = blockIdx.x*128;
    int tid = threadIdx.x, lane = tid & 31, wid = tid >> 5;
    int wm = (wid >> 2)*64, wn = (wid & 3)*32;
    uint32_t sb = (uint32_t)__cvta_generic_to_shared(smem);

    float acc[4][4][4];
    #pragma unroll
    for (int i = 0; i < 4; i++)
        #pragma unroll
        for (int j = 0; j < 4; j++)
            #pragma unroll
            for (int r = 0; r < 4; r++) acc[i][j][r] = 0.f;

    auto issue = [&](int it) {
        uint32_t st = sb + (uint32_t)(it & 1)*STG2;
        int k0 = it << 5;
        #pragma unroll
        for (int q = 0; q < 4; q++) {
            int v = tid + q*256;
            int pl = v >> 9, r = (v >> 2) & 127, kv = v & 3;
            const __nv_bfloat16* src = (pl ? pAl : pAh) + (size_t)(row0 + r)*lda + k0 + kv*8;
            CPA16(st + pl*AP2 + (uint32_t)(r*80 + kv*16), src);
        }
        #pragma unroll
        for (int q = 0; q < 4; q++) {
            int v = tid + q*256;
            int pl = v >> 9, n = (v >> 2) & 127, kv = v & 3;
            const __nv_bfloat16* src = (pl ? pBl : pBh) + (size_t)(col0 + n)*ldb + k0 + kv*8;
            CPA16(st + 2*AP2 + pl*AP2 + (uint32_t)(n*80 + kv*16), src);
        }
    };

    issue(0);
    asm volatile("cp.async.commit_group;");

    for (int it = 0; it < KIT; it++) {
        if (it + 1 < KIT) {
            __syncthreads();
            issue(it + 1);
            asm volatile("cp.async.commit_group;");
            asm volatile("cp.async.wait_group 1;");
        } else {
            asm volatile("cp.async.wait_group 0;");
        }
        __syncthreads();
        uint32_t st = sb + (uint32_t)(it & 1)*STG2;
        #pragma unroll
        for (int ks = 0; ks < 2; ks++) {
            int koff = ks*16;
            uint32_t ah[4][4], al_[4][4];
            #pragma unroll
            for (int i = 0; i < 4; i++) {
                uint32_t addr = st + (uint32_t)((wm + i*16 + (lane & 15))*80
                                  + (koff + ((lane >> 4) << 3))*2);
                LDSM4(ah[i], addr);
                LDSM4(al_[i], addr + AP2);
            }
            uint32_t bf0[4], bf1[4];
            {
                uint32_t addr = st + 2*AP2 + (uint32_t)((wn + lane)*80 + koff*2);
                LDSM4(bf0, addr);
                LDSM4(bf1, addr + 16);
            }
            #pragma unroll
            for (int i = 0; i < 4; i++)
                #pragma unroll
                for (int j = 0; j < 4; j++)
                    MMA16816(acc[i][j], ah[i], bf0[j], bf1[j]);
            #pragma unroll
            for (int i = 0; i < 4; i++)
                #pragma unroll
                for (int j = 0; j < 4; j++)
                    MMA16816(acc[i][j], al_[i], bf0[j], bf1[j]);
            {
                uint32_t addr = st + 3*AP2 + (uint32_t)((wn + lane)*80 + koff*2);
                LDSM4(bf0, addr);
                LDSM4(bf1, addr + 16);
            }
            #pragma unroll
            for (int i = 0; i < 4; i++)
                #pragma unroll
                for (int j = 0; j < 4; j++)
                    MMA16816(acc[i][j], ah[i], bf0[j], bf1[j]);
        }
    }

    #pragma unroll
    for (int i = 0; i < 4; i++) {
        int r = row0 + wm + i*16 + (lane >> 2);
        #pragma unroll
        for (int j = 0; j < 4; j++) {
            int c = col0 + wn + j*8 + ((lane & 3) << 1);
            *(float2*)&pC[(size_t)r*4096 + c] = make_float2(acc[i][j][0], acc[i][j][1]);
            *(float2*)&pC[(size_t)(r+8)*4096 + c] = make_float2(acc[i][j][2], acc[i][j][3]);
        }
    }
}

// ---------------- launch ----------------
extern "C" void kernel_launch(void* const* d_in, const int* in_sizes, int n_in,
                              void* d_out, int out_size) {
    (void)in_sizes; (void)n_in; (void)out_size;
    const float* x      = (const float*)d_in[0];
    const float* bb0_w  = (const float*)d_in[1];
    const float* bb0_b  = (const float*)d_in[2];
    const float* bb0_a  = (const float*)d_in[3];
    const float* rb1_w1 = (const float*)d_in[4];
    const float* rb1_b1 = (const float*)d_in[5];
    const float* rb1_w2 = (const float*)d_in[6];
    const float* rb1_b2 = (const float*)d_in[7];
    const float* pamb_w = (const float*)d_in[8];
    const float* pamb_b = (const float*)d_in[9];
    const float* pamb_a = (const float*)d_in[10];
    const float* pam_w  = (const float*)d_in[11];
    const float* pam_b  = (const float*)d_in[12];
    const float* pam_a  = (const float*)d_in[13];
    const float* paa_w  = (const float*)d_in[14];
    const float* paa_b  = (const float*)d_in[15];
    const float* paa_a  = (const float*)d_in[16];
    const float* rb2_w1 = (const float*)d_in[17];
    const float* rb2_b1 = (const float*)d_in[18];
    const float* rb2_w2 = (const float*)d_in[19];
    const float* rb2_b2 = (const float*)d_in[20];
    float* out = (float*)d_out;

    float *h0,*h1,*h2,*tmp,*h3,*mb,*ref,*base,*refm,*R,*scores,*T,*pmax,*psum,*E,*ninv;
    __nv_bfloat16 *ICh,*ICl,*Awh,*Awl,*refmTh,*refmTl,*mbTh,*mbTl,*baseTh,*baseTl,*Gh,*Gl;
    cudaGetSymbolAddress((void**)&h0, g_h0);
    cudaGetSymbolAddress((void**)&h1, g_h1);
    cudaGetSymbolAddress((void**)&h2, g_h2);
    cudaGetSymbolAddress((void**)&tmp, g_tmp);
    cudaGetSymbolAddress((void**)&h3, g_h3);
    cudaGetSymbolAddress((void**)&mb, g_mb);
    cudaGetSymbolAddress((void**)&ref, g_ref);
    cudaGetSymbolAddress((void**)&base, g_base);
    cudaGetSymbolAddress((void**)&refm, g_refm);
    cudaGetSymbolAddress((void**)&R, g_R);
    cudaGetSymbolAddress((void**)&scores, g_scores);
    cudaGetSymbolAddress((void**)&T, g_T);
    cudaGetSymbolAddress((void**)&ICh, g_ICh);
    cudaGetSymbolAddress((void**)&ICl, g_ICl);
    cudaGetSymbolAddress((void**)&Awh, g_Awh);
    cudaGetSymbolAddress((void**)&Awl, g_Awl);
    cudaGetSymbolAddress((void**)&refmTh, g_refmTh);
    cudaGetSymbolAddress((void**)&refmTl, g_refmTl);
    cudaGetSymbolAddress((void**)&mbTh, g_mbTh);
    cudaGetSymbolAddress((void**)&mbTl, g_mbTl);
    cudaGetSymbolAddress((void**)&baseTh, g_baseTh);
    cudaGetSymbolAddress((void**)&baseTl, g_baseTl);
    cudaGetSymbolAddress((void**)&Gh, g_Gh);
    cudaGetSymbolAddress((void**)&Gl, g_Gl);
    cudaGetSymbolAddress((void**)&E, g_E);
    cudaGetSymbolAddress((void**)&ninv, g_ninv);
    cudaGetSymbolAddress((void**)&pmax, g_pmax);
    cudaGetSymbolAddress((void**)&psum, g_psum);

    cudaFuncSetAttribute(gemm3_kernel, cudaFuncAttributeMaxDynamicSharedMemorySize, NSTG2*STG2);

    float* Craw = scores;
    auto conv3g = [&](const float* in, const float* w, const float* bias,
                      const float* alpha, const float* res, float* o, int Ci, int act) {
        int K = Ci*9;
        int split = (Ci == CIN) ? 2 : 4;     // Kh/32 integral: 288/32=9 both ways
        int Kh = K/split;
        wsplit_kernel<<<(COUT*K + 255)/256, 256>>>(w, Awh, Awl, COUT*K);
        if (Ci == CIN)
            imcol_kernel<CIN><<<dim3((P*CIN*9 + 255)/256, BB), 256>>>(in, ICh, ICl);
        else
            imcol_kernel<COUT><<<dim3((P*COUT*9 + 255)/256, BB), 256>>>(in, ICh, ICl);
        gemm3_kernel<<<dim3(P/128, 1, BB*split), 256, NSTG2*STG2>>>(
            Awh, Awl, ICh, ICl, Craw, K, K, Kh/32,
            0, (size_t)P*K, (size_t)COUT*P,
            split, Kh, (size_t)BB*COUT*P);
        epi_kernel<<<(BB*COUT*P + 255)/256, 256>>>(Craw, bias, alpha, res, o, act,
                                                   1.0f, split, (size_t)BB*COUT*P);
    };

    maxpool_kernel<<<(BB*CIN*P + 255)/256, 256>>>(x, h0);
    conv3g(h0, bb0_w, bb0_b, bb0_a, nullptr, h1, CIN, 2);
    conv3g(h1, rb1_w1, rb1_b1, nullptr, nullptr, tmp, COUT, 1);
    conv3g(tmp, rb1_w2, rb1_b2, nullptr, h1, h2, COUT, 0);

    // pyramid producers
    conv1_kernel<<<dim3(P/256, CHALF/4, BB), 256>>>(h2, pamb_w, pamb_b, pamb_a, mb, COUT, CHALF, P);
    const int Hs[4]   = {64, 57, 51, 44};
    const int loff[4] = {0, 4096, 7345, 9946};
    for (int s = 0; s < 4; s++) {
        int Ls = Hs[s]*Hs[s];
        const float* refp;
        if (s == 0) refp = h2;
        else {
            int n = BB*COUT*Ls;
            resize_kernel<<<(n + 255)/256, 256>>>(h2, ref, Hs[s]);
            refp = ref;
        }
        conv1_kernel<<<dim3((Ls + 255)/256, COUT/4, BB), 256>>>(
            refp, paa_w, paa_b, paa_a, base + (size_t)BB*COUT*loff[s], COUT, COUT, Ls);
        conv1_kernel<<<dim3((Ls + 255)/256, CHALF/4, BB), 256>>>(
            refp, pam_w, pam_b, pam_a, refm + (size_t)BB*CHALF*loff[s], COUT, CHALF, Ls);
    }

    mbT_kernel<<<(BB*P*CHALF + 255)/256, 256>>>(mb, mbTh, mbTl);
    refmT_kernel<<<dim3(LTP, BB), 64>>>(refm, refmTh, refmTl, E);
    ninv_kernel<<<dim3((LT + 255)/256, BB), 256>>>(E, ninv);
    baseT_kernel<<<(BB*COUT*LTP + 255)/256, 256>>>(base, baseTh, baseTl);

    // R[m][p] = refm^T mb  (M=LTP, N=4096, K=64)
    gemm3_kernel<<<dim3(P/128, LTP/128, BB), 256, NSTG2*STG2>>>(
        refmTh, refmTl, mbTh, mbTl, R, CHALF, CHALF, CHALF/32,
        (size_t)LTP*CHALF, (size_t)P*CHALF, (size_t)LTP*P,
        1, 0, 0);

    // scores = 9-point diagonal sum of R, normalized (l-parallel form)
    assembly_kernel<<<dim3(P/256, LT, BB), 256>>>(R, ninv, scores);

    softmax_part_kernel<<<dim3(P/256, NCH, BB), 256>>>(scores, pmax, psum);
    softmax_comb_kernel<<<dim3(P/256, BB), 256>>>(pmax, psum);

    // G = 9-point diagonal sum of attention, transposed + bf16 split
    G_kernel<<<dim3(P/32, LTP/32, BB), dim3(32,8)>>>(scores, psum, Gh, Gl);

    // out_raw = base x G  (M=128, N=4096, K=LTP), split-K x6 -> grid 384
    gemm3_kernel<<<dim3(P/128, 1, BB*6), 256, NSTG2*STG2>>>(
        baseTh, baseTl, Gh, Gl, T, LTP, LTP, (LTP/6)/32,
        (size_t)COUT*LTP, (size_t)P*LTP, (size_t)COUT*P,
        6, LTP/6, (size_t)BB*COUT*P);

    // h3 = h2 + 0.25*sum(partials)
    epi_kernel<<<(BB*COUT*P + 255)/256, 256>>>(T, nullptr, nullptr, h2, h3, 0,
                                               0.25f, 6, (size_t)BB*COUT*P);

    conv3g(h3, rb2_w1, rb2_b1, nullptr, nullptr, tmp, COUT, 1);
    conv3g(tmp, rb2_w2, rb2_b2, nullptr, h3, out, COUT, 0);
}

// round 17
// speedup vs baseline: 1.1622x; 1.1316x over previous
#include <cuda_runtime.h>
#include <cuda_bf16.h>
#include <cstdint>

// ---------------- dims ----------------
#define BB 2
#define CIN 64
#define COUT 128
#define CHALF 64
#define HIN 128
#define H 64
#define P (H*H)          // 4096
#define LT 11882
#define LTP 11904        // 93*128
#define K9 576
#define K18 1152
#define NCH 24           // softmax chunks of 512 (power of 2)
#define SCH 512

// ---------------- scratch ----------------
__device__ __align__(128) float g_h0[BB*CIN*P];
__device__ __align__(128) float g_h1[BB*COUT*P];
__device__ __align__(128) float g_h2[BB*COUT*P];
__device__ __align__(128) float g_tmp[BB*COUT*P];
__device__ __align__(128) float g_h3[BB*COUT*P];
__device__ __align__(128) float g_mb[BB*CHALF*P];
__device__ __align__(128) float g_ref[BB*COUT*3249];
__device__ __align__(128) float g_base[(size_t)BB*COUT*LT];
__device__ __align__(128) float g_refm[(size_t)BB*CHALF*LT];
__device__ __align__(128) float g_R[(size_t)BB*LTP*P];        // R = refm^T mb
__device__ __align__(128) float g_scores[(size_t)BB*LTP*P];   // scores / conv partial scratch
__device__ __align__(128) float g_T[(size_t)BB*K18*P];        // attention GEMM partials
__device__ __align__(128) __nv_bfloat16 g_ICh[(size_t)BB*P*K18];
__device__ __align__(128) __nv_bfloat16 g_ICl[(size_t)BB*P*K18];
__device__ __align__(128) __nv_bfloat16 g_Awh[COUT*K18];
__device__ __align__(128) __nv_bfloat16 g_Awl[COUT*K18];
__device__ __align__(128) __nv_bfloat16 g_refmTh[(size_t)BB*LTP*CHALF];
__device__ __align__(128) __nv_bfloat16 g_refmTl[(size_t)BB*LTP*CHALF];
__device__ __align__(128) __nv_bfloat16 g_mbTh[(size_t)BB*P*CHALF];
__device__ __align__(128) __nv_bfloat16 g_mbTl[(size_t)BB*P*CHALF];
__device__ __align__(128) __nv_bfloat16 g_baseTh[(size_t)BB*COUT*LTP];
__device__ __align__(128) __nv_bfloat16 g_baseTl[(size_t)BB*COUT*LTP];
__device__ __align__(128) __nv_bfloat16 g_Gh[(size_t)BB*P*LTP];
__device__ __align__(128) __nv_bfloat16 g_Gl[(size_t)BB*P*LTP];
__device__ __align__(128) float g_E[BB*LTP];
__device__ __align__(128) float g_ninv[BB*LTP];
__device__ __align__(128) float g_pmax[BB*NCH*P];
__device__ __align__(128) float g_psum[BB*NCH*P];
__device__ __align__(128) int4 g_lgeo[LTP];                   // {Hs, lh, lw, loff}

__device__ __forceinline__ void split2(float v, __nv_bfloat16& h, __nv_bfloat16& l) {
    h = __float2bfloat16(v);
    l = __float2bfloat16(v - __bfloat162float(h));
}

__device__ __forceinline__ void decode_l(int l, int& Hs, int& loff) {
    if (l < 4096)      { Hs = 64; loff = 0; }
    else if (l < 7345) { Hs = 57; loff = 4096; }
    else if (l < 9946) { Hs = 51; loff = 7345; }
    else               { Hs = 44; loff = 9946; }
}

// ---------------- per-l geometry table ----------------
__global__ void lgeo_kernel(int4* __restrict__ lgeo) {
    int l = blockIdx.x*256 + threadIdx.x;
    if (l >= LTP) return;
    int Hs, loff; decode_l(l < LT ? l : LT-1, Hs, loff);
    int ll = (l < LT ? l : LT-1) - loff;
    int lh = ll / Hs, lw = ll - lh*Hs;
    lgeo[l] = make_int4(Hs, lh, lw, loff);
}

// ---------------- maxpool ----------------
__global__ void maxpool_kernel(const float* __restrict__ in, float* __restrict__ out) {
    int idx = blockIdx.x*blockDim.x + threadIdx.x;
    if (idx >= BB*CIN*P) return;
    int x = idx % H; int y = (idx / H) % H; int bc = idx / P;
    const float* p = in + ((size_t)bc*HIN + 2*y)*HIN + 2*x;
    out[idx] = fmaxf(fmaxf(p[0], p[1]), fmaxf(p[HIN], p[HIN+1]));
}

// ---------------- im2col (3x3 pad1), Ci compile-time ----------------
template<int Ci>
__global__ void imcol_kernel(const float* __restrict__ in,
                             __nv_bfloat16* __restrict__ Xh, __nv_bfloat16* __restrict__ Xl) {
    constexpr int K = Ci*9;
    int idx = blockIdx.x*256 + threadIdx.x;
    int b = blockIdx.y;
    if (idx >= P*K) return;
    int k = idx % K; int p = idx / K;
    int c = k/9, r = k%9; int ky = r/3, kx = r - ky*3;
    int y = (p >> 6) + ky - 1, x = (p & 63) + kx - 1;
    float v = 0.f;
    if ((unsigned)y < H && (unsigned)x < H) v = in[((size_t)b*Ci + c)*P + y*H + x];
    __nv_bfloat16 hh, ll; split2(v, hh, ll);
    size_t o = (size_t)b*P*K + idx;
    Xh[o] = hh; Xl[o] = ll;
}

// ---------------- weight split ----------------
__global__ void wsplit_kernel(const float* __restrict__ w,
                              __nv_bfloat16* __restrict__ Ah, __nv_bfloat16* __restrict__ Al,
                              int n) {
    int idx = blockIdx.x*256 + threadIdx.x;
    if (idx >= n) return;
    __nv_bfloat16 hh, ll; split2(w[idx], hh, ll);
    Ah[idx] = hh; Al[idx] = ll;
}

// ---------------- epilogue: scale*sum(partials) + bias + act + residual ----------------
__global__ void epi_kernel(const float* __restrict__ C, const float* __restrict__ bias,
                           const float* __restrict__ alpha_p, const float* __restrict__ res,
                           float* __restrict__ out, int act, float scale,
                           int nsum, size_t sSplit) {
    int idx = blockIdx.x*256 + threadIdx.x;
    if (idx >= BB*COUT*P) return;
    int co = (idx / P) % COUT;
    float v = 0.f;
    for (int i = 0; i < nsum; i++) v += C[idx + (size_t)i*sSplit];
    v = v*scale + (bias ? bias[co] : 0.f);
    if (act == 1) v = fmaxf(v, 0.f);
    else if (act == 2) { float a = *alpha_p; v = v >= 0.f ? v : a*v; }
    if (res) v += res[idx];
    out[idx] = v;
}

// ---------------- 1x1 conv + PReLU, 4 outputs per block ----------------
__global__ void conv1_kernel(const float* __restrict__ in, const float* __restrict__ w,
                             const float* __restrict__ bias, const float* __restrict__ alpha_p,
                             float* __restrict__ out, int Ci, int Co, int Pn) {
    int p = blockIdx.x*256 + threadIdx.x;
    int o0 = blockIdx.y*4, b = blockIdx.z;
    if (p >= Pn) return;
    const float* ip = in + (size_t)b*Ci*Pn + p;
    float acc[4];
    #pragma unroll
    for (int o = 0; o < 4; o++) acc[o] = bias[o0 + o];
    #pragma unroll 4
    for (int i = 0; i < Ci; i++) {
        float t = ip[(size_t)i*Pn];
        #pragma unroll
        for (int o = 0; o < 4; o++) acc[o] += w[(size_t)(o0+o)*Ci + i] * t;
    }
    float a = *alpha_p;
    #pragma unroll
    for (int o = 0; o < 4; o++) {
        float v = acc[o];
        out[((size_t)b*Co + o0 + o)*Pn + p] = v >= 0.f ? v : a*v;
    }
}

// ---------------- bilinear resize with antialias ----------------
__global__ void resize_kernel(const float* __restrict__ in, float* __restrict__ out, int Hout) {
    int total = BB*COUT*Hout*Hout;
    int idx = blockIdx.x*blockDim.x + threadIdx.x;
    if (idx >= total) return;
    int xo = idx % Hout; int yo = (idx / Hout) % Hout; int bc = idx / (Hout*Hout);
    float inv = (float)H / (float)Hout;
    float sy = (yo + 0.5f)*inv - 0.5f;
    float sx = (xo + 0.5f)*inv - 0.5f;
    float wy[4], wx[4]; int jy[4], jx[4];
    int ny = 0, nx = 0; float sumy = 0.f, sumx = 0.f;
    int lo = (int)ceilf(sy - inv), hi = (int)floorf(sy + inv);
    if (lo < 0) lo = 0; if (hi > H-1) hi = H-1;
    for (int j = lo; j <= hi && ny < 4; j++) {
        float w = 1.0f - fabsf(sy - (float)j)/inv;
        if (w > 0.f) { wy[ny] = w; jy[ny] = j; sumy += w; ny++; }
    }
    lo = (int)ceilf(sx - inv); hi = (int)floorf(sx + inv);
    if (lo < 0) lo = 0; if (hi > H-1) hi = H-1;
    for (int j = lo; j <= hi && nx < 4; j++) {
        float w = 1.0f - fabsf(sx - (float)j)/inv;
        if (w > 0.f) { wx[nx] = w; jx[nx] = j; sumx += w; nx++; }
    }
    const float* ip = in + (size_t)bc*P;
    float acc = 0.f;
    for (int a = 0; a < ny; a++)
        for (int bx2 = 0; bx2 < nx; bx2++)
            acc += wy[a]*wx[bx2]*ip[jy[a]*H + jx[bx2]];
    out[idx] = acc / (sumy*sumx);
}

// ---------------- refmT[b][l][c] + E[b][l] ----------------
__global__ void refmT_kernel(const float* __restrict__ refm,
                             __nv_bfloat16* __restrict__ Th, __nv_bfloat16* __restrict__ Tl,
                             float* __restrict__ E) {
    int l = blockIdx.x, b = blockIdx.y, c = threadIdx.x;   // 64 threads
    float v = 0.f;
    if (l < LT) {
        int Hs, loff; decode_l(l, Hs, loff);
        int Ls = Hs*Hs;
        v = refm[(size_t)BB*CHALF*loff + ((size_t)b*CHALF + c)*Ls + (l - loff)];
    }
    __nv_bfloat16 hh, ll; split2(v, hh, ll);
    size_t o = ((size_t)b*LTP + l)*CHALF + c;
    Th[o] = hh; Tl[o] = ll;
    __shared__ float red[64];
    red[c] = v*v; __syncthreads();
    for (int s = 32; s > 0; s >>= 1) { if (c < s) red[c] += red[c+s]; __syncthreads(); }
    if (c == 0) E[(size_t)b*LTP + l] = red[0];
}

// ---------------- ninv[b][l] ----------------
__global__ void ninv_kernel(const float* __restrict__ E, const int4* __restrict__ lgeo,
                            float* __restrict__ ninv) {
    int l = blockIdx.x*256 + threadIdx.x; int b = blockIdx.y;
    if (l >= LT) return;
    int4 g = lgeo[l];
    int Hs = g.x, lh = g.y, lw = g.z;
    float a = 0.f;
    #pragma unroll
    for (int u = -1; u <= 1; u++) {
        if ((unsigned)(lh+u) >= (unsigned)Hs) continue;
        #pragma unroll
        for (int v = -1; v <= 1; v++) {
            if ((unsigned)(lw+v) >= (unsigned)Hs) continue;
            a += E[(size_t)b*LTP + l + u*Hs + v];
        }
    }
    ninv[(size_t)b*LTP + l] = 1.0f / fmaxf(sqrtf(a), 1e-4f);
}

// ---------------- mbT split ----------------
__global__ void mbT_kernel(const float* __restrict__ mb,
                           __nv_bfloat16* __restrict__ Th, __nv_bfloat16* __restrict__ Tl) {
    int idx = blockIdx.x*256 + threadIdx.x;
    if (idx >= BB*P*CHALF) return;
    int c = idx % CHALF; int p = (idx / CHALF) % P; int b = idx / (CHALF*P);
    float v = mb[((size_t)b*CHALF + c)*P + p];
    __nv_bfloat16 hh, ll; split2(v, hh, ll);
    Th[idx] = hh; Tl[idx] = ll;
}

// ---------------- baseT split ----------------
__global__ void baseT_kernel(const float* __restrict__ base,
                             __nv_bfloat16* __restrict__ Th, __nv_bfloat16* __restrict__ Tl) {
    int idx = blockIdx.x*256 + threadIdx.x;
    if (idx >= BB*COUT*LTP) return;
    int l = idx % LTP; int c = (idx / LTP) % COUT; int b = idx / (LTP*COUT);
    float v = 0.f;
    if (l < LT) {
        int Hs, loff; decode_l(l, Hs, loff);
        int Ls = Hs*Hs;
        v = base[(size_t)BB*COUT*loff + ((size_t)b*COUT + c)*Ls + (l - loff)];
    }
    __nv_bfloat16 hh, ll; split2(v, hh, ll);
    Th[idx] = hh; Tl[idx] = ll;
}

// ---------------- assembly: scores[l][p] = ninv[l] * sum_{u,v} R[l+(u,v)][p+(u,v)] ----------------
__global__ void assembly_kernel(const float* __restrict__ R, const float* __restrict__ ninv,
                                const int4* __restrict__ lgeo, float* __restrict__ scores) {
    int p = blockIdx.x*256 + threadIdx.x;
    int l = blockIdx.y, b = blockIdx.z;
    int4 g = lgeo[l];
    int Hs = g.x, lh = g.y, lw = g.z;
    int py = p >> 6, px = p & 63;
    float s = 0.f;
    #pragma unroll
    for (int u = -1; u <= 1; u++) {
        if ((unsigned)(lh+u) >= (unsigned)Hs) continue;
        if ((unsigned)(py+u) >= 64u) continue;
        #pragma unroll
        for (int v = -1; v <= 1; v++) {
            if ((unsigned)(lw+v) >= (unsigned)Hs) continue;
            if ((unsigned)(px+v) >= 64u) continue;
            s += R[((size_t)b*LTP + l + u*Hs + v)*P + p + u*64 + v];
        }
    }
    scores[((size_t)b*LTP + l)*P + p] = s * ninv[(size_t)b*LTP + l];
}

// ---------------- softmax pass 1 (stores exp in place) ----------------
__global__ void softmax_part_kernel(float* __restrict__ scores,
                                    float* __restrict__ pmax, float* __restrict__ psum) {
    int p = blockIdx.x*256 + threadIdx.x;
    int c = blockIdx.y, b = blockIdx.z;
    int l0 = c*SCH, l1 = l0 + SCH; if (l1 > LT) l1 = LT;
    float* s = scores + (size_t)b*LTP*P + p;
    float m = -1e30f;
    for (int l = l0; l < l1; l++) m = fmaxf(m, s[(size_t)l*P]);
    float sum = 0.f;
    for (int l = l0; l < l1; l++) {
        float e = __expf(10.f*(s[(size_t)l*P] - m));
        s[(size_t)l*P] = e;
        sum += e;
    }
    pmax[((size_t)b*NCH + c)*P + p] = m;
    psum[((size_t)b*NCH + c)*P + p] = sum;
}

__global__ void softmax_comb_kernel(const float* __restrict__ pmax, float* __restrict__ psum) {
    int p = blockIdx.x*256 + threadIdx.x; int b = blockIdx.y;
    float M = -1e30f;
    for (int c = 0; c < NCH; c++) M = fmaxf(M, pmax[((size_t)b*NCH + c)*P + p]);
    float S = 0.f;
    for (int c = 0; c < NCH; c++)
        S += psum[((size_t)b*NCH + c)*P + p] * __expf(10.f*(pmax[((size_t)b*NCH + c)*P + p] - M));
    float invS = 1.0f / S;
    for (int c = 0; c < NCH; c++)
        psum[((size_t)b*NCH + c)*P + p] =
            __expf(10.f*(pmax[((size_t)b*NCH + c)*P + p] - M)) * invS;
}

// ---------------- G[b][p][m] = sum9 att, bf16 hi/lo, transposed ----------------
__global__ void G_kernel(const float* __restrict__ scores, const float* __restrict__ psum,
                         const int4* __restrict__ lgeo,
                         __nv_bfloat16* __restrict__ Th, __nv_bfloat16* __restrict__ Tl) {
    __shared__ float t[32][33];
    int p0 = blockIdx.x*32, m0 = blockIdx.y*32, b = blockIdx.z;
    int tx = threadIdx.x, ty = threadIdx.y;
    const float* sc = scores + (size_t)b*LTP*P;
    const float* ps = psum + (size_t)b*NCH*P;
    #pragma unroll
    for (int i = 0; i < 4; i++) {
        int m = m0 + ty + i*8;
        float g = 0.f;
        if (m < LT) {
            int4 lg = lgeo[m];
            int Hs = lg.x, mh = lg.y, mw = lg.z;
            int p = p0 + tx; int py = p >> 6, px = p & 63;
            #pragma unroll
            for (int u = -1; u <= 1; u++) {
                if ((unsigned)(mh+u) >= (unsigned)Hs) continue;
                if ((unsigned)(py+u) >= 64u) continue;
                #pragma unroll
                for (int v = -1; v <= 1; v++) {
                    if ((unsigned)(mw+v) >= (unsigned)Hs) continue;
                    if ((unsigned)(px+v) >= 64u) continue;
                    int lp = m + u*Hs + v; int pp = p + u*64 + v;
                    g += sc[(size_t)lp*P + pp] * ps[(size_t)(lp >> 9)*P + pp];
                }
            }
        }
        t[ty + i*8][tx] = g;
    }
    __syncthreads();
    #pragma unroll
    for (int i = 0; i < 4; i++) {
        int p = p0 + ty + i*8;
        float v = t[tx][ty + i*8];
        __nv_bfloat16 hh, lo; split2(v, hh, lo);
        size_t o = ((size_t)b*P + p)*LTP + m0 + tx;
        Th[o] = hh; Tl[o] = lo;
    }
}

// ---------------- bf16x3 mma.sync GEMM: CTA 128x128, warp 64x32, 2-stage, occ 2 ----------------
#define AP2 10240
#define STG2 (4*AP2)
#define NSTG2 2

#define LDSM4(R, addr) asm volatile( \
    "ldmatrix.sync.aligned.m8n8.x4.shared.b16 {%0,%1,%2,%3},[%4];" \
    : "=r"((R)[0]),"=r"((R)[1]),"=r"((R)[2]),"=r"((R)[3]) : "r"(addr))
#define MMA16816(d, a, b0, b1) asm volatile( \
    "mma.sync.aligned.m16n8k16.row.col.f32.bf16.bf16.f32 " \
    "{%0,%1,%2,%3},{%4,%5,%6,%7},{%8,%9},{%0,%1,%2,%3};" \
    : "+f"((d)[0]),"+f"((d)[1]),"+f"((d)[2]),"+f"((d)[3]) \
    : "r"((a)[0]),"r"((a)[1]),"r"((a)[2]),"r"((a)[3]),"r"(b0),"r"(b1))
#define CPA16(dst, src) asm volatile( \
    "cp.async.cg.shared.global [%0],[%1],16;" :: "r"(dst),"l"(src))

__global__ __launch_bounds__(256, 2) void gemm3_kernel(
    const __nv_bfloat16* __restrict__ Ah, const __nv_bfloat16* __restrict__ Al,
    const __nv_bfloat16* __restrict__ Bh, const __nv_bfloat16* __restrict__ Bl,
    float* __restrict__ C, int lda, int ldb, int KIT,
    size_t sA, size_t sB, size_t sC,
    int nsplit, int koffE, size_t sSplit)
{
    extern __shared__ char smem[];
    int zz = blockIdx.z;
    int half = zz % nsplit, b = zz / nsplit;
    int kofs = half * koffE;
    const __nv_bfloat16* pAh = Ah + (size_t)b*sA + kofs;
    const __nv_bfloat16* pAl = Al + (size_t)b*sA + kofs;
    const __nv_bfloat16* pBh = Bh + (size_t)b*sB + kofs;
    const __nv_bfloat16* pBl = Bl + (size_t)b*sB + kofs;
    float* pC = C + (size_t)b*sC + (size_t)half*sSplit;
    int row0 = blockIdx.y*128, col0 = blockIdx.x*128;
    int tid = threadIdx.x, lane = tid & 31, wid = tid >> 5;
    int wm = (wid >> 2)*64, wn = (wid & 3)*32;
    uint32_t sb = (uint32_t)__cvta_generic_to_shared(smem);

    float acc[4][4][4];
    #pragma unroll
    for (int i = 0; i < 4; i++)
        #pragma unroll
        for (int j = 0; j < 4; j++)
            #pragma unroll
            for (int r = 0; r < 4; r++) acc[i][j][r] = 0.f;

    auto issue = [&](int it) {
        uint32_t st = sb + (uint32_t)(it & 1)*STG2;
        int k0 = it << 5;
        #pragma unroll
        for (int q = 0; q < 4; q++) {
            int v = tid + q*256;
            int pl = v >> 9, r = (v >> 2) & 127, kv = v & 3;
            const __nv_bfloat16* src = (pl ? pAl : pAh) + (size_t)(row0 + r)*lda + k0 + kv*8;
            CPA16(st + pl*AP2 + (uint32_t)(r*80 + kv*16), src);
        }
        #pragma unroll
        for (int q = 0; q < 4; q++) {
            int v = tid + q*256;
            int pl = v >> 9, n = (v >> 2) & 127, kv = v & 3;
            const __nv_bfloat16* src = (pl ? pBl : pBh) + (size_t)(col0 + n)*ldb + k0 + kv*8;
            CPA16(st + 2*AP2 + pl*AP2 + (uint32_t)(n*80 + kv*16), src);
        }
    };

    issue(0);
    asm volatile("cp.async.commit_group;");

    for (int it = 0; it < KIT; it++) {
        if (it + 1 < KIT) {
            __syncthreads();
            issue(it + 1);
            asm volatile("cp.async.commit_group;");
            asm volatile("cp.async.wait_group 1;");
        } else {
            asm volatile("cp.async.wait_group 0;");
        }
        __syncthreads();
        uint32_t st = sb + (uint32_t)(it & 1)*STG2;
        #pragma unroll
        for (int ks = 0; ks < 2; ks++) {
            int koff = ks*16;
            uint32_t ah[4][4], al_[4][4];
            #pragma unroll
            for (int i = 0; i < 4; i++) {
                uint32_t addr = st + (uint32_t)((wm + i*16 + (lane & 15))*80
                                  + (koff + ((lane >> 4) << 3))*2);
                LDSM4(ah[i], addr);
                LDSM4(al_[i], addr + AP2);
            }
            uint32_t bf0[4], bf1[4];
            {
                uint32_t addr = st + 2*AP2 + (uint32_t)((wn + lane)*80 + koff*2);
                LDSM4(bf0, addr);
                LDSM4(bf1, addr + 16);
            }
            #pragma unroll
            for (int i = 0; i < 4; i++)
                #pragma unroll
                for (int j = 0; j < 4; j++)
                    MMA16816(acc[i][j], ah[i], bf0[j], bf1[j]);
            #pragma unroll
            for (int i = 0; i < 4; i++)
                #pragma unroll
                for (int j = 0; j < 4; j++)
                    MMA16816(acc[i][j], al_[i], bf0[j], bf1[j]);
            {
                uint32_t addr = st + 3*AP2 + (uint32_t)((wn + lane)*80 + koff*2);
                LDSM4(bf0, addr);
                LDSM4(bf1, addr + 16);
            }
            #pragma unroll
            for (int i = 0; i < 4; i++)
                #pragma unroll
                for (int j = 0; j < 4; j++)
                    MMA16816(acc[i][j], ah[i], bf0[j], bf1[j]);
        }
    }

    #pragma unroll
    for (int i = 0; i < 4; i++) {
        int r = row0 + wm + i*16 + (lane >> 2);
        #pragma unroll
        for (int j = 0; j < 4; j++) {
            int c = col0 + wn + j*8 + ((lane & 3) << 1);
            *(float2*)&pC[(size_t)r*4096 + c] = make_float2(acc[i][j][0], acc[i][j][1]);
            *(float2*)&pC[(size_t)(r+8)*4096 + c] = make_float2(acc[i][j][2], acc[i][j][3]);
        }
    }
}

// ---------------- launch ----------------
extern "C" void kernel_launch(void* const* d_in, const int* in_sizes, int n_in,
                              void* d_out, int out_size) {
    (void)in_sizes; (void)n_in; (void)out_size;
    const float* x      = (const float*)d_in[0];
    const float* bb0_w  = (const float*)d_in[1];
    const float* bb0_b  = (const float*)d_in[2];
    const float* bb0_a  = (const float*)d_in[3];
    const float* rb1_w1 = (const float*)d_in[4];
    const float* rb1_b1 = (const float*)d_in[5];
    const float* rb1_w2 = (const float*)d_in[6];
    const float* rb1_b2 = (const float*)d_in[7];
    const float* pamb_w = (const float*)d_in[8];
    const float* pamb_b = (const float*)d_in[9];
    const float* pamb_a = (const float*)d_in[10];
    const float* pam_w  = (const float*)d_in[11];
    const float* pam_b  = (const float*)d_in[12];
    const float* pam_a  = (const float*)d_in[13];
    const float* paa_w  = (const float*)d_in[14];
    const float* paa_b  = (const float*)d_in[15];
    const float* paa_a  = (const float*)d_in[16];
    const float* rb2_w1 = (const float*)d_in[17];
    const float* rb2_b1 = (const float*)d_in[18];
    const float* rb2_w2 = (const float*)d_in[19];
    const float* rb2_b2 = (const float*)d_in[20];
    float* out = (float*)d_out;

    float *h0,*h1,*h2,*tmp,*h3,*mb,*ref,*base,*refm,*R,*scores,*T,*pmax,*psum,*E,*ninv;
    __nv_bfloat16 *ICh,*ICl,*Awh,*Awl,*refmTh,*refmTl,*mbTh,*mbTl,*baseTh,*baseTl,*Gh,*Gl;
    int4 *lgeo;
    cudaGetSymbolAddress((void**)&h0, g_h0);
    cudaGetSymbolAddress((void**)&h1, g_h1);
    cudaGetSymbolAddress((void**)&h2, g_h2);
    cudaGetSymbolAddress((void**)&tmp, g_tmp);
    cudaGetSymbolAddress((void**)&h3, g_h3);
    cudaGetSymbolAddress((void**)&mb, g_mb);
    cudaGetSymbolAddress((void**)&ref, g_ref);
    cudaGetSymbolAddress((void**)&base, g_base);
    cudaGetSymbolAddress((void**)&refm, g_refm);
    cudaGetSymbolAddress((void**)&R, g_R);
    cudaGetSymbolAddress((void**)&scores, g_scores);
    cudaGetSymbolAddress((void**)&T, g_T);
    cudaGetSymbolAddress((void**)&ICh, g_ICh);
    cudaGetSymbolAddress((void**)&ICl, g_ICl);
    cudaGetSymbolAddress((void**)&Awh, g_Awh);
    cudaGetSymbolAddress((void**)&Awl, g_Awl);
    cudaGetSymbolAddress((void**)&refmTh, g_refmTh);
    cudaGetSymbolAddress((void**)&refmTl, g_refmTl);
    cudaGetSymbolAddress((void**)&mbTh, g_mbTh);
    cudaGetSymbolAddress((void**)&mbTl, g_mbTl);
    cudaGetSymbolAddress((void**)&baseTh, g_baseTh);
    cudaGetSymbolAddress((void**)&baseTl, g_baseTl);
    cudaGetSymbolAddress((void**)&Gh, g_Gh);
    cudaGetSymbolAddress((void**)&Gl, g_Gl);
    cudaGetSymbolAddress((void**)&E, g_E);
    cudaGetSymbolAddress((void**)&ninv, g_ninv);
    cudaGetSymbolAddress((void**)&pmax, g_pmax);
    cudaGetSymbolAddress((void**)&psum, g_psum);
    cudaGetSymbolAddress((void**)&lgeo, g_lgeo);

    cudaFuncSetAttribute(gemm3_kernel, cudaFuncAttributeMaxDynamicSharedMemorySize, NSTG2*STG2);

    lgeo_kernel<<<(LTP + 255)/256, 256>>>(lgeo);

    float* Craw = scores;
    auto conv3g = [&](const float* in, const float* w, const float* bias,
                      const float* alpha, const float* res, float* o, int Ci, int act) {
        int K = Ci*9;
        int split = (Ci == CIN) ? 2 : 4;
        int Kh = K/split;
        wsplit_kernel<<<(COUT*K + 255)/256, 256>>>(w, Awh, Awl, COUT*K);
        if (Ci == CIN)
            imcol_kernel<CIN><<<dim3((P*CIN*9 + 255)/256, BB), 256>>>(in, ICh, ICl);
        else
            imcol_kernel<COUT><<<dim3((P*COUT*9 + 255)/256, BB), 256>>>(in, ICh, ICl);
        gemm3_kernel<<<dim3(P/128, 1, BB*split), 256, NSTG2*STG2>>>(
            Awh, Awl, ICh, ICl, Craw, K, K, Kh/32,
            0, (size_t)P*K, (size_t)COUT*P,
            split, Kh, (size_t)BB*COUT*P);
        epi_kernel<<<(BB*COUT*P + 255)/256, 256>>>(Craw, bias, alpha, res, o, act,
                                                   1.0f, split, (size_t)BB*COUT*P);
    };

    maxpool_kernel<<<(BB*CIN*P + 255)/256, 256>>>(x, h0);
    conv3g(h0, bb0_w, bb0_b, bb0_a, nullptr, h1, CIN, 2);
    conv3g(h1, rb1_w1, rb1_b1, nullptr, nullptr, tmp, COUT, 1);
    conv3g(tmp, rb1_w2, rb1_b2, nullptr, h1, h2, COUT, 0);

    // pyramid producers
    conv1_kernel<<<dim3(P/256, CHALF/4, BB), 256>>>(h2, pamb_w, pamb_b, pamb_a, mb, COUT, CHALF, P);
    const int Hs[4]   = {64, 57, 51, 44};
    const int loff[4] = {0, 4096, 7345, 9946};
    for (int s = 0; s < 4; s++) {
        int Ls = Hs[s]*Hs[s];
        const float* refp;
        if (s == 0) refp = h2;
        else {
            int n = BB*COUT*Ls;
            resize_kernel<<<(n + 255)/256, 256>>>(h2, ref, Hs[s]);
            refp = ref;
        }
        conv1_kernel<<<dim3((Ls + 255)/256, COUT/4, BB), 256>>>(
            refp, paa_w, paa_b, paa_a, base + (size_t)BB*COUT*loff[s], COUT, COUT, Ls);
        conv1_kernel<<<dim3((Ls + 255)/256, CHALF/4, BB), 256>>>(
            refp, pam_w, pam_b, pam_a, refm + (size_t)BB*CHALF*loff[s], COUT, CHALF, Ls);
    }

    mbT_kernel<<<(BB*P*CHALF + 255)/256, 256>>>(mb, mbTh, mbTl);
    refmT_kernel<<<dim3(LTP, BB), 64>>>(refm, refmTh, refmTl, E);
    ninv_kernel<<<dim3((LT + 255)/256, BB), 256>>>(E, lgeo, ninv);
    baseT_kernel<<<(BB*COUT*LTP + 255)/256, 256>>>(base, baseTh, baseTl);

    // R[m][p] = refm^T mb  (M=LTP, N=4096, K=64)
    gemm3_kernel<<<dim3(P/128, LTP/128, BB), 256, NSTG2*STG2>>>(
        refmTh, refmTl, mbTh, mbTl, R, CHALF, CHALF, CHALF/32,
        (size_t)LTP*CHALF, (size_t)P*CHALF, (size_t)LTP*P,
        1, 0, 0);

    // scores = 9-point diagonal sum of R, normalized (l-parallel, LUT-driven)
    assembly_kernel<<<dim3(P/256, LT, BB), 256>>>(R, ninv, lgeo, scores);

    softmax_part_kernel<<<dim3(P/256, NCH, BB), 256>>>(scores, pmax, psum);
    softmax_comb_kernel<<<dim3(P/256, BB), 256>>>(pmax, psum);

    // G = 9-point diagonal sum of attention, transposed + bf16 split
    G_kernel<<<dim3(P/32, LTP/32, BB), dim3(32,8)>>>(scores, psum, lgeo, Gh, Gl);

    // out_raw = base x G  (M=128, N=4096, K=LTP), split-K x6
    gemm3_kernel<<<dim3(P/128, 1, BB*6), 256, NSTG2*STG2>>>(
        baseTh, baseTl, Gh, Gl, T, LTP, LTP, (LTP/6)/32,
        (size_t)COUT*LTP, (size_t)P*LTP, (size_t)COUT*P,
        6, LTP/6, (size_t)BB*COUT*P);

    // h3 = h2 + 0.25*sum(partials)
    epi_kernel<<<(BB*COUT*P + 255)/256, 256>>>(T, nullptr, nullptr, h2, h3, 0,
                                               0.25f, 6, (size_t)BB*COUT*P);

    conv3g(h3, rb2_w1, rb2_b1, nullptr, nullptr, tmp, COUT, 1);
    conv3g(tmp, rb2_w2, rb2_b2, nullptr, h3, out, COUT, 0);
}